// round 1
// baseline (speedup 1.0000x reference)
#include <cuda_runtime.h>
#include <cstdint>
#include <cstddef>

// Problem dims
#define BB 256
#define TT 128
#define EE 300
#define HH 512
#define DD 1024
#define KTOT 812          // E + H
#define G4 2048           // 4*H

// ---------------- device scratch (static, no allocations) ----------------
__device__ float g_h[2][2][BB][HH];   // [lstm][pingpong][b][j]
__device__ float g_c[2][BB][HH];      // [lstm][b][j]
__device__ float g_mlp[2][BB][DD];    // MLP intermediates

// ---------------- packed f32x2 helpers ----------------
__device__ __forceinline__ uint64_t pack2(float lo, float hi) {
    uint64_t r; asm("mov.b64 %0, {%1, %2};" : "=l"(r) : "f"(lo), "f"(hi)); return r;
}
__device__ __forceinline__ uint64_t dup2(float v) {
    uint64_t r; asm("mov.b64 %0, {%1, %1};" : "=l"(r) : "f"(v)); return r;
}
__device__ __forceinline__ void fma2(uint64_t& d, uint64_t a, uint64_t b) {
    asm("fma.rn.f32x2 %0, %1, %2, %0;" : "+l"(d) : "l"(a), "l"(b));
}
__device__ __forceinline__ void unpack2(uint64_t v, float& lo, float& hi) {
    asm("mov.b64 {%0, %1}, %2;" : "=f"(lo), "=f"(hi) : "l"(v));
}

// ---------------- fast activations (~1e-6 rel err) ----------------
__device__ __forceinline__ float ex2f_(float x) {
    float y; asm("ex2.approx.f32 %0, %1;" : "=f"(y) : "f"(x)); return y;
}
__device__ __forceinline__ float rcpf_(float x) {
    float y; asm("rcp.approx.f32 %0, %1;" : "=f"(y) : "f"(x)); return y;
}
__device__ __forceinline__ float sigmoidf_(float x) {
    // 1/(1+exp(-x)); saturates cleanly at 0/1 (inf -> rcp -> 0)
    return rcpf_(1.0f + ex2f_(-1.4426950408889634f * x));
}
__device__ __forceinline__ float tanhf_(float x) {
    x = fminf(fmaxf(x, -15.0f), 15.0f);   // avoid inf*0 in the rational form
    float e = ex2f_(2.8853900817779268f * x);   // exp(2x)
    return (e - 1.0f) * rcpf_(e + 1.0f);
}

// ---------------- init: zero h (both buffers) and c ----------------
__global__ void __launch_bounds__(256) init_state_kernel() {
    int idx = blockIdx.x * 256 + threadIdx.x;
    const int NH = 2 * 2 * BB * HH;      // 524288
    const int NC = 2 * BB * HH;          // 262144
    if (idx < NH) {
        (&g_h[0][0][0][0])[idx] = 0.0f;
    } else {
        int r = idx - NH;
        if (r < NC) (&g_c[0][0][0])[r] = 0.0f;
    }
}

// ---------------- one LSTM timestep for BOTH LSTMs ----------------
// z = [x_t, h_{t-1}] @ W + b, gates i,j,f,o ; mask on t < length.
// GEMM: M=256 (b), N=512 (j) x 4 gates, K=812.
// Tile: BM=64 (b), BN=32 (j), 4 gates. grid (16 j-tiles, 4 b-tiles, 2 lstm) = 128 CTAs.
__global__ void __launch_bounds__(256) lstm_step_kernel(
    const float* __restrict__ xL, const float* __restrict__ xR,
    const float* __restrict__ WL, const float* __restrict__ WR,
    const float* __restrict__ bL, const float* __restrict__ bR,
    const int* __restrict__ lenL, const int* __restrict__ lenR,
    int t)
{
    const int l = blockIdx.z;
    const float* __restrict__ x    = l ? xR : xL;
    const float* __restrict__ W    = l ? WR : WL;
    const float* __restrict__ bias = l ? bR : bL;
    const int*   __restrict__ len  = l ? lenR : lenL;
    const float* __restrict__ hin  = &g_h[l][t & 1][0][0];
    float*       __restrict__ hout = &g_h[l][(t + 1) & 1][0][0];

    __shared__ __align__(16) float As[16][64];      // [k][b-row]
    __shared__ __align__(16) float Bs[4][16][32];   // [gate][k][j]

    const int tid = threadIdx.x;
    const int tx = tid & 15, ty = tid >> 4;
    const int r0 = ty * 4;        // 4 b-rows per thread
    const int jp = tx * 2;        // 1 j-pair per thread
    const int bx = blockIdx.x, by = blockIdx.y;

    uint64_t acc[4][4];           // [row][gate], f32x2 pair over j
#pragma unroll
    for (int i = 0; i < 4; ++i)
#pragma unroll
        for (int g = 0; g < 4; ++g) acc[i][g] = 0ull;

    for (int k0 = 0; k0 < KTOT; k0 += 16) {
        // --- load A tile: 64 rows x 16 k, one float4 per thread ---
        {
            int row = tid >> 2, kq = tid & 3;
            int k = k0 + kq * 4;
            int b = by * 64 + row;
            float4 v = make_float4(0.f, 0.f, 0.f, 0.f);
            if (k < EE) {
                // x[b][t][k], layout [B][T][E]; E%4==0 so float4 stays in-row
                v = *(const float4*)(x + (size_t)b * (TT * EE) + (size_t)t * EE + k);
            } else if (k < KTOT) {
                v = *(const float4*)(hin + (size_t)b * HH + (k - EE));
            }
            As[kq * 4 + 0][row] = v.x;
            As[kq * 4 + 1][row] = v.y;
            As[kq * 4 + 2][row] = v.z;
            As[kq * 4 + 3][row] = v.w;
        }
        // --- load B tiles: 4 gates x 16 k x 32 j = 512 float4 / 2 per thread ---
        for (int i = tid; i < 512; i += 256) {
            int g = i >> 7, rem = i & 127;
            int k = rem >> 3, jq = (rem & 7) * 4;
            int kr = k0 + k;
            float4 v = make_float4(0.f, 0.f, 0.f, 0.f);
            if (kr < KTOT)
                v = *(const float4*)(W + (size_t)kr * G4 + g * HH + bx * 32 + jq);
            *(float4*)&Bs[g][k][jq] = v;
        }
        __syncthreads();

#pragma unroll
        for (int kk = 0; kk < 16; ++kk) {
            float4 a = *(const float4*)&As[kk][r0];
            uint64_t a0 = dup2(a.x), a1 = dup2(a.y), a2 = dup2(a.z), a3 = dup2(a.w);
#pragma unroll
            for (int g = 0; g < 4; ++g) {
                uint64_t bv = *(const uint64_t*)&Bs[g][kk][jp];
                fma2(acc[0][g], a0, bv);
                fma2(acc[1][g], a1, bv);
                fma2(acc[2][g], a2, bv);
                fma2(acc[3][g], a3, bv);
            }
        }
        __syncthreads();
    }

    // --- epilogue: gates + state update ---
#pragma unroll
    for (int i = 0; i < 4; ++i) {
        int b = by * 64 + r0 + i;
        int jj = bx * 32 + jp;
        float z[4][2];
#pragma unroll
        for (int g = 0; g < 4; ++g) {
            unpack2(acc[i][g], z[g][0], z[g][1]);
            z[g][0] += bias[g * HH + jj];
            z[g][1] += bias[g * HH + jj + 1];
        }
        bool upd = (t < len[b]);
#pragma unroll
        for (int q = 0; q < 2; ++q) {
            int j = jj + q;
            float c_old = g_c[l][b][j];
            float cn, hn;
            if (upd) {
                float iv = sigmoidf_(z[0][q]);
                float gv = tanhf_(z[1][q]);
                float fv = sigmoidf_(z[2][q] + 1.0f);   // forget bias
                float ov = sigmoidf_(z[3][q]);
                cn = c_old * fv + iv * gv;
                hn = tanhf_(cn) * ov;
            } else {
                cn = c_old;
                hn = hin[(size_t)b * HH + j];
            }
            g_c[l][b][j] = cn;
            hout[(size_t)b * HH + j] = hn;
        }
    }
}

// ---------------- MLP layer: C = relu(A @ W), M=256, N=1024, K=1024 ----------------
// asel: 0 = concat(hL,hR) from g_h[.][0], 1 = g_mlp[0], 2 = g_mlp[1]
// csel: 0 = g_mlp[0], 1 = g_mlp[1], 2 = dout
__global__ void __launch_bounds__(256) mlp_kernel(
    int asel, const float* __restrict__ W, float* __restrict__ dout, int csel)
{
    const int bx = blockIdx.x, by = blockIdx.y;
    __shared__ __align__(16) float As[16][64];
    __shared__ __align__(16) float Bs[16][64];
    const int tid = threadIdx.x;
    const int tx = tid & 15, ty = tid >> 4;

    uint64_t acc[4][2];
#pragma unroll
    for (int i = 0; i < 4; ++i) { acc[i][0] = 0ull; acc[i][1] = 0ull; }

    const float* Abase = (asel == 1) ? &g_mlp[0][0][0] : &g_mlp[1][0][0];

    for (int k0 = 0; k0 < DD; k0 += 16) {
        {
            int row = tid >> 2, kq = tid & 3;
            int b = by * 64 + row;
            int k = k0 + kq * 4;
            float4 v;
            if (asel == 0) {
                int lsel = k >> 9, j = k & 511;   // concat: [hL | hR]
                v = *(const float4*)&g_h[lsel][0][b][j];
            } else {
                v = *(const float4*)(Abase + (size_t)b * DD + k);
            }
            As[kq * 4 + 0][row] = v.x;
            As[kq * 4 + 1][row] = v.y;
            As[kq * 4 + 2][row] = v.z;
            As[kq * 4 + 3][row] = v.w;
        }
        {
            int k = tid >> 4, j4 = (tid & 15) * 4;
            *(float4*)&Bs[k][j4] = *(const float4*)(W + (size_t)(k0 + k) * DD + bx * 64 + j4);
        }
        __syncthreads();
#pragma unroll
        for (int kk = 0; kk < 16; ++kk) {
            float4 a  = *(const float4*)&As[kk][ty * 4];
            float4 bv = *(const float4*)&Bs[kk][tx * 4];
            uint64_t p0 = pack2(bv.x, bv.y), p1 = pack2(bv.z, bv.w);
            uint64_t d0 = dup2(a.x), d1 = dup2(a.y), d2 = dup2(a.z), d3 = dup2(a.w);
            fma2(acc[0][0], d0, p0); fma2(acc[0][1], d0, p1);
            fma2(acc[1][0], d1, p0); fma2(acc[1][1], d1, p1);
            fma2(acc[2][0], d2, p0); fma2(acc[2][1], d2, p1);
            fma2(acc[3][0], d3, p0); fma2(acc[3][1], d3, p1);
        }
        __syncthreads();
    }

    float* C = (csel == 0) ? &g_mlp[0][0][0] : (csel == 1) ? &g_mlp[1][0][0] : dout;
#pragma unroll
    for (int i = 0; i < 4; ++i) {
        int b = by * 64 + ty * 4 + i;
        int n = bx * 64 + tx * 4;
        float v0, v1, v2, v3;
        unpack2(acc[i][0], v0, v1);
        unpack2(acc[i][1], v2, v3);
        C[(size_t)b * DD + n + 0] = fmaxf(v0, 0.0f);
        C[(size_t)b * DD + n + 1] = fmaxf(v1, 0.0f);
        C[(size_t)b * DD + n + 2] = fmaxf(v2, 0.0f);
        C[(size_t)b * DD + n + 3] = fmaxf(v3, 0.0f);
    }
}

// ---------------- launch ----------------
extern "C" void kernel_launch(void* const* d_in, const int* in_sizes, int n_in,
                              void* d_out, int out_size)
{
    const float* xL      = (const float*)d_in[0];   // [256,128,300]
    const float* xR      = (const float*)d_in[1];
    const int*   lenL    = (const int*)  d_in[2];   // [256]
    const int*   lenR    = (const int*)  d_in[3];
    const float* WL      = (const float*)d_in[4];   // [812,2048]
    const float* bL      = (const float*)d_in[5];   // [2048]
    const float* WR      = (const float*)d_in[6];
    const float* bR      = (const float*)d_in[7];
    const float* trans_w = (const float*)d_in[8];   // [1024,1024]
    const float* hidden  = (const float*)d_in[9];   // [2,1024,1024]
    float* out = (float*)d_out;                      // [256,1024]

    (void)in_sizes; (void)n_in; (void)out_size;

    // zero h (both ping-pong buffers) and c
    init_state_kernel<<<3072, 256>>>();

    // 128 sequential LSTM steps (both LSTMs per launch)
    for (int t = 0; t < TT; ++t) {
        lstm_step_kernel<<<dim3(16, 4, 2), 256>>>(xL, xR, WL, WR, bL, bR, lenL, lenR, t);
    }

    // MLP: relu(concat @ trans_w) -> relu(@hidden0) -> relu(@hidden1) -> out
    mlp_kernel<<<dim3(16, 4), 256>>>(0, trans_w, nullptr, 0);
    mlp_kernel<<<dim3(16, 4), 256>>>(1, hidden, nullptr, 1);
    mlp_kernel<<<dim3(16, 4), 256>>>(2, hidden + (size_t)DD * DD, out, 2);
}

// round 5
// speedup vs baseline: 1.7533x; 1.7533x over previous
#include <cuda_runtime.h>
#include <cstdint>
#include <cstddef>

// Problem dims
#define BB 256
#define TT 128
#define EE 300
#define HH 512
#define DD 1024
#define G4 2048
#define TCH 4           // timestep chunk for zx precompute

// ---------------- device scratch (static, no allocations) ----------------
__device__ float g_h[2][2][BB][HH];        // [lstm][pingpong][b][j]
__device__ float g_c[2][BB][HH];           // [lstm][b][j]
__device__ float g_mlp[2][BB][DD];         // MLP intermediates
__device__ float g_zx[2][TCH][BB][G4];     // precomputed x@Wx + b (16.8 MB)

// ---------------- packed f32x2 helpers ----------------
__device__ __forceinline__ uint64_t pack2(float lo, float hi) {
    uint64_t r; asm("mov.b64 %0, {%1, %2};" : "=l"(r) : "f"(lo), "f"(hi)); return r;
}
__device__ __forceinline__ uint64_t dup2(float v) {
    uint64_t r; asm("mov.b64 %0, {%1, %1};" : "=l"(r) : "f"(v)); return r;
}
__device__ __forceinline__ void fma2(uint64_t& d, uint64_t a, uint64_t b) {
    asm("fma.rn.f32x2 %0, %1, %2, %0;" : "+l"(d) : "l"(a), "l"(b));
}
__device__ __forceinline__ void unpack2(uint64_t v, float& lo, float& hi) {
    asm("mov.b64 {%0, %1}, %2;" : "=f"(lo), "=f"(hi) : "l"(v));
}

// ---------------- cp.async helpers ----------------
__device__ __forceinline__ void cp16(void* smem, const void* g, bool valid) {
    uint32_t s = (uint32_t)__cvta_generic_to_shared(smem);
    int sz = valid ? 16 : 0;
    asm volatile("cp.async.cg.shared.global [%0], [%1], 16, %2;"
                 :: "r"(s), "l"(g), "r"(sz));
}
__device__ __forceinline__ void cp_commit() {
    asm volatile("cp.async.commit_group;");
}
__device__ __forceinline__ void cp_wait0() {
    asm volatile("cp.async.wait_group 0;");
}

// ---------------- fast activations (~1e-6 rel err) ----------------
__device__ __forceinline__ float ex2f_(float x) {
    float y; asm("ex2.approx.f32 %0, %1;" : "=f"(y) : "f"(x)); return y;
}
__device__ __forceinline__ float rcpf_(float x) {
    float y; asm("rcp.approx.f32 %0, %1;" : "=f"(y) : "f"(x)); return y;
}
__device__ __forceinline__ float sigmoidf_(float x) {
    return rcpf_(1.0f + ex2f_(-1.4426950408889634f * x));
}
__device__ __forceinline__ float tanhf_(float x) {
    x = fminf(fmaxf(x, -15.0f), 15.0f);
    float e = ex2f_(2.8853900817779268f * x);
    return (e - 1.0f) * rcpf_(e + 1.0f);
}

// ---------------- init: zero h (both buffers) and c ----------------
__global__ void __launch_bounds__(256) init_state_kernel() {
    int idx = blockIdx.x * 256 + threadIdx.x;
    const int NH = 2 * 2 * BB * HH;      // 524288
    const int NC = 2 * BB * HH;          // 262144
    if (idx < NH) {
        (&g_h[0][0][0][0])[idx] = 0.0f;
    } else {
        int r = idx - NH;
        if (r < NC) (&g_c[0][0][0])[r] = 0.0f;
    }
}

// =====================================================================
// Precompute zx[l][tc][b][:] = x[b][t0+tc][:] @ Wx + bias  for TCH steps
// GEMM per lstm: M = 256*TCH (m = b*TCH+tc), N = 2048, K = 300 (pad 320)
// Tile BM=64, BN=64, 128 threads, thread-tile 4 rows x 8 cols.
// grid (32, BB*TCH/64, 2)
// =====================================================================
__global__ void __launch_bounds__(128) precompute_kernel(
    const float* __restrict__ xL, const float* __restrict__ xR,
    const float* __restrict__ WL, const float* __restrict__ WR,
    const float* __restrict__ bL, const float* __restrict__ bR, int t0)
{
    const int l = blockIdx.z;
    const float* __restrict__ x    = l ? xR : xL;
    const float* __restrict__ W    = l ? WR : WL;
    const float* __restrict__ bias = l ? bR : bL;

    __shared__ __align__(16) float As[2][32][64];
    __shared__ __align__(16) float Bs[2][32][64];

    const int tid = threadIdx.x;
    const int tx = tid & 7, ty = tid >> 3;     // tx: 8 col-groups, ty: 16 row-groups
    const int n0 = blockIdx.x * 64;
    const int m0 = blockIdx.y * 64;

    uint64_t acc[4][4];
#pragma unroll
    for (int i = 0; i < 4; ++i)
#pragma unroll
        for (int p = 0; p < 4; ++p) acc[i][p] = 0ull;

    float4 av[4];

    auto ldA = [&](int k0) {
#pragma unroll
        for (int p = 0; p < 4; ++p) {
            int m = m0 + ty + p * 16;
            int b = m / TCH, tc = m % TCH;
            int k = k0 + tx * 4;
            float4 v = make_float4(0.f, 0.f, 0.f, 0.f);
            if (k < EE)
                v = *(const float4*)(x + ((size_t)b * TT + (t0 + tc)) * EE + k);
            av[p] = v;
        }
    };
    auto stA = [&](int buf) {
#pragma unroll
        for (int p = 0; p < 4; ++p) {
            int rsw = (ty + p * 16) ^ (tx * 4);   // xor-swizzle: conflict-free STS+LDS
            As[buf][tx * 4 + 0][rsw] = av[p].x;
            As[buf][tx * 4 + 1][rsw] = av[p].y;
            As[buf][tx * 4 + 2][rsw] = av[p].z;
            As[buf][tx * 4 + 3][rsw] = av[p].w;
        }
    };
    auto ldB = [&](int k0, int buf) {
#pragma unroll
        for (int p = 0; p < 4; ++p) {
            int f4 = p * 128 + tid;
            int k = f4 >> 4, jq = f4 & 15;
            bool v = (k0 + k) < EE;
            const float* src = W + (size_t)(v ? (k0 + k) : 0) * G4 + n0 + jq * 4;
            cp16(&Bs[buf][k][jq * 4], src, v);
        }
    };
    auto comp = [&](int buf) {
#pragma unroll
        for (int kk = 0; kk < 32; ++kk) {
            float4 a = *(const float4*)&As[buf][kk][(ty * 4) ^ (4 * (kk >> 2))];
            uint64_t d0 = dup2(a.x), d1 = dup2(a.y), d2 = dup2(a.z), d3 = dup2(a.w);
            const float* bp = &Bs[buf][kk][0];
            uint64_t b0 = *(const uint64_t*)(bp + tx * 4);
            uint64_t b1 = *(const uint64_t*)(bp + tx * 4 + 2);
            uint64_t b2 = *(const uint64_t*)(bp + tx * 4 + 32);
            uint64_t b3 = *(const uint64_t*)(bp + tx * 4 + 34);
            fma2(acc[0][0], d0, b0); fma2(acc[0][1], d0, b1); fma2(acc[0][2], d0, b2); fma2(acc[0][3], d0, b3);
            fma2(acc[1][0], d1, b0); fma2(acc[1][1], d1, b1); fma2(acc[1][2], d1, b2); fma2(acc[1][3], d1, b3);
            fma2(acc[2][0], d2, b0); fma2(acc[2][1], d2, b1); fma2(acc[2][2], d2, b2); fma2(acc[2][3], d2, b3);
            fma2(acc[3][0], d3, b0); fma2(acc[3][1], d3, b1); fma2(acc[3][2], d3, b2); fma2(acc[3][3], d3, b3);
        }
    };

    const int NCH = 10;  // 10*32 = 320 >= 300
    ldA(0); ldB(0, 0); cp_commit(); stA(0);
    for (int c = 0; c < NCH; ++c) {
        int buf = c & 1;
        cp_wait0();
        __syncthreads();
        if (c + 1 < NCH) { ldA((c + 1) * 32); ldB((c + 1) * 32, buf ^ 1); cp_commit(); }
        comp(buf);
        if (c + 1 < NCH) stA(buf ^ 1);
    }

    // epilogue: add bias, write zx
#pragma unroll
    for (int i = 0; i < 4; ++i) {
        int m = m0 + ty * 4 + i;
        int b = m / TCH, tc = m % TCH;
        float* zrow = &g_zx[l][tc][b][0];
#pragma unroll
        for (int p = 0; p < 4; ++p) {
            int col = n0 + tx * 4 + (p >> 1) * 32 + (p & 1) * 2;
            float lo, hi; unpack2(acc[i][p], lo, hi);
            float2 o; o.x = lo + bias[col]; o.y = hi + bias[col + 1];
            *(float2*)(zrow + col) = o;
        }
    }
}

// =====================================================================
// LSTM step: zh = h @ Wh (K=512), z = zh + zx[t], gates, state update.
// CTA tile: 64 b-rows x (4 gates x 16 j). 128 threads, thread-tile
// 4 rows x 4 gates x 2 j. grid (32 j-tiles, 4 b-tiles, 2 lstm) = 256 CTAs.
// =====================================================================
__global__ void __launch_bounds__(128) lstm_step_kernel(
    const float* __restrict__ WL, const float* __restrict__ WR,
    const int* __restrict__ lenL, const int* __restrict__ lenR, int t)
{
    const int l = blockIdx.z;
    const float* __restrict__ W   = l ? WR : WL;
    const int*   __restrict__ len = l ? lenR : lenL;
    const float* __restrict__ hin  = &g_h[l][t & 1][0][0];
    float*       __restrict__ hout = &g_h[l][(t + 1) & 1][0][0];

    __shared__ __align__(16) float As[2][32][64];
    __shared__ __align__(16) float Bs[2][4][32][16];

    const int tid = threadIdx.x;
    const int tx = tid & 7, ty = tid >> 3;
    const int j0 = blockIdx.x * 16;
    const int b0 = blockIdx.y * 64;

    uint64_t acc[4][4];   // [row][gate]
#pragma unroll
    for (int i = 0; i < 4; ++i)
#pragma unroll
        for (int g = 0; g < 4; ++g) acc[i][g] = 0ull;

    float4 av[4];

    auto ldA = [&](int k0) {
#pragma unroll
        for (int p = 0; p < 4; ++p)
            av[p] = *(const float4*)(hin + (size_t)(b0 + ty + p * 16) * HH + k0 + tx * 4);
    };
    auto stA = [&](int buf) {
#pragma unroll
        for (int p = 0; p < 4; ++p) {
            int rsw = (ty + p * 16) ^ (tx * 4);
            As[buf][tx * 4 + 0][rsw] = av[p].x;
            As[buf][tx * 4 + 1][rsw] = av[p].y;
            As[buf][tx * 4 + 2][rsw] = av[p].z;
            As[buf][tx * 4 + 3][rsw] = av[p].w;
        }
    };
    auto ldB = [&](int k0, int buf) {
#pragma unroll
        for (int p = 0; p < 4; ++p) {
            int f4 = p * 128 + tid;                 // 512 float4 = [4g][32k][4jq]
            int g = f4 >> 7, k = (f4 >> 2) & 31, jq = f4 & 3;
            const float* src = W + (size_t)(EE + k0 + k) * G4 + g * HH + j0 + jq * 4;
            cp16(&Bs[buf][g][k][jq * 4], src, true);
        }
    };
    auto comp = [&](int buf) {
#pragma unroll
        for (int kk = 0; kk < 32; ++kk) {
            float4 a = *(const float4*)&As[buf][kk][(ty * 4) ^ (4 * (kk >> 2))];
            uint64_t d0 = dup2(a.x), d1 = dup2(a.y), d2 = dup2(a.z), d3 = dup2(a.w);
#pragma unroll
            for (int g = 0; g < 4; ++g) {
                uint64_t bv = *(const uint64_t*)&Bs[buf][g][kk][tx * 2];
                fma2(acc[0][g], d0, bv);
                fma2(acc[1][g], d1, bv);
                fma2(acc[2][g], d2, bv);
                fma2(acc[3][g], d3, bv);
            }
        }
    };

    const int NCH = 16;  // 16*32 = 512
    ldA(0); ldB(0, 0); cp_commit(); stA(0);
    for (int c = 0; c < NCH; ++c) {
        int buf = c & 1;
        cp_wait0();
        __syncthreads();
        if (c + 1 < NCH) { ldA((c + 1) * 32); ldB((c + 1) * 32, buf ^ 1); cp_commit(); }
        comp(buf);
        if (c + 1 < NCH) stA(buf ^ 1);
    }

    // --- epilogue: z = zh + zx, gates, state update ---
    const int tc = t & (TCH - 1);
    const int jj = j0 + tx * 2;
#pragma unroll
    for (int i = 0; i < 4; ++i) {
        int b = b0 + ty * 4 + i;
        bool upd = (t < len[b]);
        float z[4][2];
#pragma unroll
        for (int g = 0; g < 4; ++g) {
            float lo, hi; unpack2(acc[i][g], lo, hi);
            float2 zx = *(const float2*)&g_zx[l][tc][b][g * HH + jj];
            z[g][0] = lo + zx.x;
            z[g][1] = hi + zx.y;
        }
#pragma unroll
        for (int q = 0; q < 2; ++q) {
            int j = jj + q;
            float c_old = g_c[l][b][j];
            float cn, hn;
            if (upd) {
                float iv = sigmoidf_(z[0][q]);
                float gv = tanhf_(z[1][q]);
                float fv = sigmoidf_(z[2][q] + 1.0f);   // forget bias
                float ov = sigmoidf_(z[3][q]);
                cn = c_old * fv + iv * gv;
                hn = tanhf_(cn) * ov;
            } else {
                cn = c_old;
                hn = hin[(size_t)b * HH + j];
            }
            g_c[l][b][j] = cn;
            hout[(size_t)b * HH + j] = hn;
        }
    }
}

// ---------------- MLP layer: C = relu(A @ W), M=256, N=1024, K=1024 ----------------
__global__ void __launch_bounds__(256) mlp_kernel(
    int asel, const float* __restrict__ W, float* __restrict__ dout, int csel)
{
    const int bx = blockIdx.x, by = blockIdx.y;
    __shared__ __align__(16) float As[16][64];
    __shared__ __align__(16) float Bs[16][64];
    const int tid = threadIdx.x;
    const int tx = tid & 15, ty = tid >> 4;

    uint64_t acc[4][2];
#pragma unroll
    for (int i = 0; i < 4; ++i) { acc[i][0] = 0ull; acc[i][1] = 0ull; }

    const float* Abase = (asel == 1) ? &g_mlp[0][0][0] : &g_mlp[1][0][0];

    for (int k0 = 0; k0 < DD; k0 += 16) {
        {
            int row = tid >> 2, kq = tid & 3;
            int b = by * 64 + row;
            int k = k0 + kq * 4;
            float4 v;
            if (asel == 0) {
                int lsel = k >> 9, j = k & 511;
                v = *(const float4*)&g_h[lsel][0][b][j];
            } else {
                v = *(const float4*)(Abase + (size_t)b * DD + k);
            }
            As[kq * 4 + 0][row] = v.x;
            As[kq * 4 + 1][row] = v.y;
            As[kq * 4 + 2][row] = v.z;
            As[kq * 4 + 3][row] = v.w;
        }
        {
            int k = tid >> 4, j4 = (tid & 15) * 4;
            *(float4*)&Bs[k][j4] = *(const float4*)(W + (size_t)(k0 + k) * DD + bx * 64 + j4);
        }
        __syncthreads();
#pragma unroll
        for (int kk = 0; kk < 16; ++kk) {
            float4 a  = *(const float4*)&As[kk][ty * 4];
            float4 bv = *(const float4*)&Bs[kk][tx * 4];
            uint64_t p0 = pack2(bv.x, bv.y), p1 = pack2(bv.z, bv.w);
            uint64_t d0 = dup2(a.x), d1 = dup2(a.y), d2 = dup2(a.z), d3 = dup2(a.w);
            fma2(acc[0][0], d0, p0); fma2(acc[0][1], d0, p1);
            fma2(acc[1][0], d1, p0); fma2(acc[1][1], d1, p1);
            fma2(acc[2][0], d2, p0); fma2(acc[2][1], d2, p1);
            fma2(acc[3][0], d3, p0); fma2(acc[3][1], d3, p1);
        }
        __syncthreads();
    }

    float* C = (csel == 0) ? &g_mlp[0][0][0] : (csel == 1) ? &g_mlp[1][0][0] : dout;
#pragma unroll
    for (int i = 0; i < 4; ++i) {
        int b = by * 64 + ty * 4 + i;
        int n = bx * 64 + tx * 4;
        float v0, v1, v2, v3;
        unpack2(acc[i][0], v0, v1);
        unpack2(acc[i][1], v2, v3);
        C[(size_t)b * DD + n + 0] = fmaxf(v0, 0.0f);
        C[(size_t)b * DD + n + 1] = fmaxf(v1, 0.0f);
        C[(size_t)b * DD + n + 2] = fmaxf(v2, 0.0f);
        C[(size_t)b * DD + n + 3] = fmaxf(v3, 0.0f);
    }
}

// ---------------- launch ----------------
extern "C" void kernel_launch(void* const* d_in, const int* in_sizes, int n_in,
                              void* d_out, int out_size)
{
    const float* xL      = (const float*)d_in[0];   // [256,128,300]
    const float* xR      = (const float*)d_in[1];
    const int*   lenL    = (const int*)  d_in[2];   // [256]
    const int*   lenR    = (const int*)  d_in[3];
    const float* WL      = (const float*)d_in[4];   // [812,2048]
    const float* bL      = (const float*)d_in[5];   // [2048]
    const float* WR      = (const float*)d_in[6];
    const float* bR      = (const float*)d_in[7];
    const float* trans_w = (const float*)d_in[8];   // [1024,1024]
    const float* hidden  = (const float*)d_in[9];   // [2,1024,1024]
    float* out = (float*)d_out;                      // [256,1024]

    (void)in_sizes; (void)n_in; (void)out_size;

    init_state_kernel<<<3072, 256>>>();

    for (int t0 = 0; t0 < TT; t0 += TCH) {
        precompute_kernel<<<dim3(32, (BB * TCH) / 64, 2), 128>>>(xL, xR, WL, WR, bL, bR, t0);
        for (int t = t0; t < t0 + TCH; ++t) {
            lstm_step_kernel<<<dim3(32, 4, 2), 128>>>(WL, WR, lenL, lenR, t);
        }
    }

    mlp_kernel<<<dim3(16, 4), 256>>>(0, trans_w, nullptr, 0);
    mlp_kernel<<<dim3(16, 4), 256>>>(1, hidden, nullptr, 1);
    mlp_kernel<<<dim3(16, 4), 256>>>(2, hidden + (size_t)DD * DD, out, 2);
}